// round 2
// baseline (speedup 1.0000x reference)
#include <cuda_runtime.h>
#include <cuda_bf16.h>

// Problem shape (fixed by the dataset): B=8, R=C=1024, 16 instance ids.
static constexpr int RDIM = 1024;
static constexpr int CDIM = 1024;
static constexpr int PER_BATCH = RDIM * CDIM;
static constexpr int MAX_INST = 16;
static constexpr int B_MAX = 16;

// Scratch: per-(batch, instance) valid-pixel counts.
__device__ int g_sizes[B_MAX * MAX_INST];

__global__ void pc_zero_kernel() {
    int t = threadIdx.x;
    if (t < B_MAX * MAX_INST) g_sizes[t] = 0;
}

// Pass 1: histogram of valid pixels per (batch, instance).
// Each block handles 256 threads * 8 pixels = 2048 contiguous pixels.
// 2048 divides PER_BATCH, so a block never straddles a batch boundary.
__global__ __launch_bounds__(256) void pc_count_kernel(
    const int* __restrict__ nz, const int* __restrict__ gt)
{
    __shared__ int hist[MAX_INST];
    if (threadIdx.x < MAX_INST) hist[threadIdx.x] = 0;
    __syncthreads();

    const long long base = (long long)blockIdx.x * 2048 + threadIdx.x * 4;
    const int b = (int)(base / PER_BATCH);

    #pragma unroll
    for (int it = 0; it < 2; ++it) {
        long long i = base + (long long)it * 1024;  // 256 threads * 4
        int4 nz4 = *reinterpret_cast<const int4*>(nz + i);
        int4 gt4 = *reinterpret_cast<const int4*>(gt + i);
        if (nz4.x > 0 && gt4.x > 0) atomicAdd(&hist[gt4.x], 1);
        if (nz4.y > 0 && gt4.y > 0) atomicAdd(&hist[gt4.y], 1);
        if (nz4.z > 0 && gt4.z > 0) atomicAdd(&hist[gt4.z], 1);
        if (nz4.w > 0 && gt4.w > 0) atomicAdd(&hist[gt4.w], 1);
    }
    __syncthreads();

    if (threadIdx.x < MAX_INST) {
        int v = hist[threadIdx.x];
        if (v > 0) atomicAdd(&g_sizes[b * MAX_INST + threadIdx.x], v);
    }
}

__device__ __forceinline__ float sigmoidf_fast(float x) {
    return 1.0f / (1.0f + __expf(-x));
}

// Pass 2: per-pixel weights + offset-agreement, vectorized 4 pixels/thread.
__global__ __launch_bounds__(256) void pc_main_kernel(
    const int*   __restrict__ nz,
    const float* __restrict__ pred,
    const float* __restrict__ off,     // (B, 2, R, C)
    const int*   __restrict__ gt,
    float*       __restrict__ out_pw,  // (B, R, C)
    float*       __restrict__ out_ow)  // (B, 2, R, C)
{
    const long long i0 = ((long long)blockIdx.x * blockDim.x + threadIdx.x) * 4;
    const int b   = (int)(i0 / PER_BATCH);
    const int rem = (int)(i0 - (long long)b * PER_BATCH);
    const int r   = rem >> 10;          // / CDIM
    const int c0  = rem & (CDIM - 1);

    const int4   nz4   = *reinterpret_cast<const int4*>(nz + i0);
    const int4   gt4   = *reinterpret_cast<const int4*>(gt + i0);
    const float4 pr4   = *reinterpret_cast<const float4*>(pred + i0);
    const long long ob = (long long)b * 2 * PER_BATCH + rem;
    const float4 oy4   = *reinterpret_cast<const float4*>(off + ob);
    const float4 ox4   = *reinterpret_cast<const float4*>(off + ob + PER_BATCH);

    const int* __restrict__ gt_b = gt + (long long)b * PER_BATCH;
    const int* __restrict__ cnt_b = &g_sizes[b * MAX_INST];

    float pw[4], w0[4], w1[4];
    const int   gts[4] = {gt4.x, gt4.y, gt4.z, gt4.w};
    const int   nzs[4] = {nz4.x, nz4.y, nz4.z, nz4.w};
    const float prs[4] = {pr4.x, pr4.y, pr4.z, pr4.w};
    const float oys[4] = {oy4.x, oy4.y, oy4.z, oy4.w};
    const float oxs[4] = {ox4.x, ox4.y, ox4.z, ox4.w};
    const float rf = (float)r;

    #pragma unroll
    for (int k = 0; k < 4; ++k) {
        const int g = gts[k];
        const bool mask = (nzs[k] > 0) && (g > 0);
        float w = 0.0f;
        float agree_w = 0.0f;
        if (mask) {
            const int cnt = cnt_b[g];
            w = 1.0f / fmaxf((float)cnt, 1.0f);
            // follow the offset (round-half-to-even like jnp.round)
            float tyf = rintf(rf + oys[k]);
            float txf = rintf((float)(c0 + k) + oxs[k]);
            tyf = fminf(fmaxf(tyf, 0.0f), (float)(RDIM - 1));
            txf = fminf(fmaxf(txf, 0.0f), (float)(CDIM - 1));
            const int ty = (int)tyf;
            const int tx = (int)txf;
            const int gtt = __ldg(&gt_b[ty * CDIM + tx]);
            agree_w = (gtt == g) ? w : 0.0f;
        }
        pw[k] = w * sigmoidf_fast(prs[k]);
        w0[k] = agree_w * oys[k];
        w1[k] = agree_w * oxs[k];
    }

    *reinterpret_cast<float4*>(out_pw + i0)           = make_float4(pw[0], pw[1], pw[2], pw[3]);
    *reinterpret_cast<float4*>(out_ow + ob)           = make_float4(w0[0], w0[1], w0[2], w0[3]);
    *reinterpret_cast<float4*>(out_ow + ob + PER_BATCH) = make_float4(w1[0], w1[1], w1[2], w1[3]);
}

extern "C" void kernel_launch(void* const* d_in, const int* in_sizes, int n_in,
                              void* d_out, int out_size) {
    const int*   nz   = (const int*)  d_in[0];  // non_zeros_map (B,R,C) int32
    const float* pred = (const float*)d_in[1];  // pixel_pred    (B,R,C) f32
    const float* off  = (const float*)d_in[2];  // offset_pred   (B,2,R,C) f32
    const int*   gt   = (const int*)  d_in[3];  // pixel_gt      (B,R,C) int32

    const long long N = in_sizes[0];            // B*R*C
    float* out_pw = (float*)d_out;              // pixel_weight  (B,R,C)
    float* out_ow = (float*)d_out + N;          // offset_weight (B,2,R,C)

    pc_zero_kernel<<<1, 256>>>();

    const int count_blocks = (int)(N / 2048);
    pc_count_kernel<<<count_blocks, 256>>>(nz, gt);

    const int main_blocks = (int)(N / (256 * 4));
    pc_main_kernel<<<main_blocks, 256>>>(nz, pred, off, gt, out_pw, out_ow);
}